// round 6
// baseline (speedup 1.0000x reference)
#include <cuda_runtime.h>
#include <cuda_bf16.h>
#include <math.h>

#define NROWS 384
#define SLEN  1024
#define CIN   256
#define CH    32
#define NH    8
#define HC    256   // NH*CH

// Scratch (no cudaMalloc allowed).
__device__ float g_q_buf[NROWS * HC];
__device__ float g_o_buf[NROWS * HC];
__device__ float g_k_buf[(size_t)NROWS * SLEN * CH];
__device__ float g_v_buf[(size_t)NROWS * SLEN * CH];
// Pre-split weights (bf16 hi/lo) for tensor-core paths.
__device__ __nv_bfloat16 g_WgHi[CIN * HC], g_WgLo[CIN * HC];
__device__ __nv_bfloat16 g_WoHi[HC * CIN], g_WoLo[HC * CIN];
__device__ __nv_bfloat16 g_WkvHi[CIN * 64], g_WkvLo[CIN * 64];  // Wk|Wv combined

// ---------------------------------------------------------------------------
// Kernel 0: split Wg, Wo, Wk|Wv into bf16 hi/lo
// ---------------------------------------------------------------------------
__global__ void wconv_kernel(const float* __restrict__ Wg,
                             const float* __restrict__ Wo,
                             const float* __restrict__ Wk,
                             const float* __restrict__ Wv) {
    int i = (blockIdx.x * 256 + threadIdx.x) * 4;  // 65536 elems per big matrix
    {
        float4 v = *reinterpret_cast<const float4*>(Wg + i);
        __nv_bfloat162 h01 = __floats2bfloat162_rn(v.x, v.y);
        __nv_bfloat162 h23 = __floats2bfloat162_rn(v.z, v.w);
        __nv_bfloat162 l01 = __floats2bfloat162_rn(v.x - __low2float(h01),
                                                   v.y - __high2float(h01));
        __nv_bfloat162 l23 = __floats2bfloat162_rn(v.z - __low2float(h23),
                                                   v.w - __high2float(h23));
        *reinterpret_cast<__nv_bfloat162*>(g_WgHi + i)     = h01;
        *reinterpret_cast<__nv_bfloat162*>(g_WgHi + i + 2) = h23;
        *reinterpret_cast<__nv_bfloat162*>(g_WgLo + i)     = l01;
        *reinterpret_cast<__nv_bfloat162*>(g_WgLo + i + 2) = l23;
    }
    {
        float4 v = *reinterpret_cast<const float4*>(Wo + i);
        __nv_bfloat162 h01 = __floats2bfloat162_rn(v.x, v.y);
        __nv_bfloat162 h23 = __floats2bfloat162_rn(v.z, v.w);
        __nv_bfloat162 l01 = __floats2bfloat162_rn(v.x - __low2float(h01),
                                                   v.y - __high2float(h01));
        __nv_bfloat162 l23 = __floats2bfloat162_rn(v.z - __low2float(h23),
                                                   v.w - __high2float(h23));
        *reinterpret_cast<__nv_bfloat162*>(g_WoHi + i)     = h01;
        *reinterpret_cast<__nv_bfloat162*>(g_WoHi + i + 2) = h23;
        *reinterpret_cast<__nv_bfloat162*>(g_WoLo + i)     = l01;
        *reinterpret_cast<__nv_bfloat162*>(g_WoLo + i + 2) = l23;
    }
    if (i < CIN * 64) {  // combined Wk|Wv: row k, col j (j<32 => Wk, else Wv)
        int k = i >> 6, j = i & 63;
        float4 v = (j < 32)
            ? *reinterpret_cast<const float4*>(Wk + k * CH + j)
            : *reinterpret_cast<const float4*>(Wv + k * CH + (j - 32));
        __nv_bfloat162 h01 = __floats2bfloat162_rn(v.x, v.y);
        __nv_bfloat162 h23 = __floats2bfloat162_rn(v.z, v.w);
        __nv_bfloat162 l01 = __floats2bfloat162_rn(v.x - __low2float(h01),
                                                   v.y - __high2float(h01));
        __nv_bfloat162 l23 = __floats2bfloat162_rn(v.z - __low2float(h23),
                                                   v.w - __high2float(h23));
        *reinterpret_cast<__nv_bfloat162*>(g_WkvHi + i)     = h01;
        *reinterpret_cast<__nv_bfloat162*>(g_WkvHi + i + 2) = h23;
        *reinterpret_cast<__nv_bfloat162*>(g_WkvLo + i)     = l01;
        *reinterpret_cast<__nv_bfloat162*>(g_WkvLo + i + 2) = l23;
    }
}

// ---------------------------------------------------------------------------
// Kernel 1: masked mean over S, then q = (mean @ Wq) * C^-0.5
// ---------------------------------------------------------------------------
__global__ void q_kernel(const float* __restrict__ m,
                         const float* __restrict__ mask,
                         const float* __restrict__ Wq) {
    int n = blockIdx.x, t = threadIdx.x;
    const float* mrow = m + (size_t)n * SLEN * CIN;
    const float* mk   = mask + (size_t)n * SLEN;

    float qs = 0.f;
    #pragma unroll 4
    for (int s = 0; s < SLEN; s++)
        qs = fmaf(mrow[(size_t)s * CIN + t], mk[s], qs);
    float ms = 0.f;
    for (int s = t; s < SLEN; s += 256) ms += mk[s];

    __shared__ float red[256];
    red[t] = ms;
    __syncthreads();
    for (int off = 128; off > 0; off >>= 1) {
        if (t < off) red[t] += red[t + off];
        __syncthreads();
    }
    float denom = red[0] + 1e-10f;

    __shared__ float qm[CIN];
    qm[t] = qs / denom;
    __syncthreads();

    float acc = 0.f;
    #pragma unroll 8
    for (int c = 0; c < CIN; c++) acc = fmaf(qm[c], Wq[c * HC + t], acc);
    g_q_buf[n * HC + t] = acc * 0.17677669529663687f;
}

// ---------------------------------------------------------------------------
// MMA helpers (bf16x3 split)
// ---------------------------------------------------------------------------
__device__ __forceinline__ void ldsm4(unsigned r[4], unsigned addr) {
    asm volatile("ldmatrix.sync.aligned.m8n8.x4.shared.b16 {%0,%1,%2,%3}, [%4];"
        : "=r"(r[0]), "=r"(r[1]), "=r"(r[2]), "=r"(r[3]) : "r"(addr));
}
__device__ __forceinline__ void ldsm4t(unsigned r[4], unsigned addr) {
    asm volatile("ldmatrix.sync.aligned.m8n8.x4.trans.shared.b16 {%0,%1,%2,%3}, [%4];"
        : "=r"(r[0]), "=r"(r[1]), "=r"(r[2]), "=r"(r[3]) : "r"(addr));
}
__device__ __forceinline__ void mma_bf16(float c[4], const unsigned a[4],
                                         unsigned b0, unsigned b1) {
    asm volatile("mma.sync.aligned.m16n8k16.row.col.f32.bf16.bf16.f32 "
        "{%0,%1,%2,%3}, {%4,%5,%6,%7}, {%8,%9}, {%0,%1,%2,%3};"
        : "+f"(c[0]), "+f"(c[1]), "+f"(c[2]), "+f"(c[3])
        : "r"(a[0]), "r"(a[1]), "r"(a[2]), "r"(a[3]), "r"(b0), "r"(b1));
}

// split a float4 into bf16 hi/lo pairs and store to smem
__device__ __forceinline__ void split_store(char* ph, char* pl, float4 v) {
    __nv_bfloat162 h01 = __floats2bfloat162_rn(v.x, v.y);
    __nv_bfloat162 h23 = __floats2bfloat162_rn(v.z, v.w);
    __nv_bfloat162 l01 = __floats2bfloat162_rn(v.x - __low2float(h01),
                                               v.y - __high2float(h01));
    __nv_bfloat162 l23 = __floats2bfloat162_rn(v.z - __low2float(h23),
                                               v.w - __high2float(h23));
    reinterpret_cast<__nv_bfloat162*>(ph)[0] = h01;
    reinterpret_cast<__nv_bfloat162*>(ph)[1] = h23;
    reinterpret_cast<__nv_bfloat162*>(pl)[0] = l01;
    reinterpret_cast<__nv_bfloat162*>(pl)[1] = l23;
}

// ---------------------------------------------------------------------------
// Kernel 2: k|v = m @ (Wk|Wv), bf16x3 tensor path.
// CTA = 128 tokens, 256 threads (8 warps, each 16 rows x 64 cols).
// ---------------------------------------------------------------------------
#define KA_STR  264
#define KAH_OFF 0                 // 128 x 264 bf16 = 67584 B
#define KAL_OFF 67584
#define KB_STR  72
#define KBH_OFF 135168            // 16 x 72 bf16 = 2304 B
#define KBL_OFF 137472
#define KV_SMEM 139776

__global__ void __launch_bounds__(256)
kv_kernel(const float* __restrict__ m) {
    extern __shared__ char smc[];
    unsigned sbase = (unsigned)__cvta_generic_to_shared(smc);
    int t = threadIdx.x;
    int lane = t & 31, wm = t >> 5;
    long r0g = (long)blockIdx.x * 128;

    // load m tile [128][256] fp32, split into hi/lo smem
    #pragma unroll
    for (int i = 0; i < 32; i++) {
        int idx = t + i * 256;
        int row = idx >> 6;
        int c4  = (idx & 63) << 2;
        float4 v = *reinterpret_cast<const float4*>(m + (r0g + row) * CIN + c4);
        split_store(smc + KAH_OFF + (row * KA_STR + c4) * 2,
                    smc + KAL_OFF + (row * KA_STR + c4) * 2, v);
    }
    __syncthreads();

    float acc[8][4];
    #pragma unroll
    for (int i = 0; i < 8; i++)
        #pragma unroll
        for (int j = 0; j < 4; j++) acc[i][j] = 0.f;

    for (int kk = 0; kk < 256; kk += 16) {
        if (t < 128) {  // B chunk [16][64] hi+lo
            int row = t >> 3;
            int c8  = (t & 7) << 3;
            *reinterpret_cast<uint4*>(smc + KBH_OFF + (row * KB_STR + c8) * 2) =
                *reinterpret_cast<const uint4*>(g_WkvHi + (kk + row) * 64 + c8);
            *reinterpret_cast<uint4*>(smc + KBL_OFF + (row * KB_STR + c8) * 2) =
                *reinterpret_cast<const uint4*>(g_WkvLo + (kk + row) * 64 + c8);
        }
        __syncthreads();

        unsigned ah[4], al[4];
        unsigned aaddr = sbase + KAH_OFF +
            ((wm * 16 + (lane & 15)) * KA_STR + kk + ((lane >> 4) << 3)) * 2;
        ldsm4(ah, aaddr);
        ldsm4(al, aaddr + (KAL_OFF - KAH_OFF));

        #pragma unroll
        for (int nb = 0; nb < 4; nb++) {
            unsigned baddr = sbase + KBH_OFF +
                ((lane & 15) * KB_STR + nb * 16 + ((lane >> 4) << 3)) * 2;
            unsigned bh[4], bl[4];
            ldsm4t(bh, baddr);
            ldsm4t(bl, baddr + (KBL_OFF - KBH_OFF));
            mma_bf16(acc[nb * 2],     ah, bh[0], bh[1]);
            mma_bf16(acc[nb * 2],     ah, bl[0], bl[1]);
            mma_bf16(acc[nb * 2],     al, bh[0], bh[1]);
            mma_bf16(acc[nb * 2 + 1], ah, bh[2], bh[3]);
            mma_bf16(acc[nb * 2 + 1], ah, bl[2], bl[3]);
            mma_bf16(acc[nb * 2 + 1], al, bh[2], bh[3]);
        }
        __syncthreads();
    }

    // write k (cols 0..31) and v (cols 32..63)
    #pragma unroll
    for (int nb = 0; nb < 4; nb++) {
        #pragma unroll
        for (int half = 0; half < 2; half++) {
            int col = nb * 16 + half * 8 + (lane & 3) * 2;
            int r0  = wm * 16 + (lane >> 2);
            float* f = acc[nb * 2 + half];
            float* dst = (col < CH) ? (g_k_buf + ((r0g + r0) * CH + col))
                                    : (g_v_buf + ((r0g + r0) * CH + col - CH));
            *reinterpret_cast<float2*>(dst) = make_float2(f[0], f[1]);
            dst += 8 * CH;
            *reinterpret_cast<float2*>(dst) = make_float2(f[2], f[3]);
        }
    }
}

// ---------------------------------------------------------------------------
// Kernel 3: attention (logits + softmax + p@v), fp32
// ---------------------------------------------------------------------------
__global__ void __launch_bounds__(256, 2)
attn_kernel(const float* __restrict__ mask) {
    int n = blockIdx.x, t = threadIdx.x;
    __shared__ float q_sm[HC];
    __shared__ float p_sm[NH * SLEN];

    q_sm[t] = g_q_buf[n * HC + t];
    __syncthreads();

    const float* krow = g_k_buf + (size_t)n * SLEN * CH;
    const float* vrow = g_v_buf + (size_t)n * SLEN * CH;
    const float* mk   = mask + (size_t)n * SLEN;

    for (int s = t; s < SLEN; s += 256) {
        float kreg[32];
        #pragma unroll
        for (int q = 0; q < 8; q++)
            *reinterpret_cast<float4*>(kreg + q * 4) =
                *reinterpret_cast<const float4*>(krow + (size_t)s * CH + q * 4);
        float bias = 1e9f * (mk[s] - 1.0f);
        #pragma unroll
        for (int h = 0; h < NH; h++) {
            float d = 0.f;
            #pragma unroll
            for (int j = 0; j < 32; j++) d = fmaf(q_sm[h * 32 + j], kreg[j], d);
            p_sm[h * SLEN + s] = d + bias;
        }
    }
    __syncthreads();

    int h = t >> 5, lane = t & 31;
    float mx = -3.0e38f;
    for (int s = lane; s < SLEN; s += 32) mx = fmaxf(mx, p_sm[h * SLEN + s]);
    #pragma unroll
    for (int off = 16; off > 0; off >>= 1)
        mx = fmaxf(mx, __shfl_xor_sync(0xffffffffu, mx, off));

    float sum = 0.f;
    for (int s = lane; s < SLEN; s += 32) {
        float e = __expf(p_sm[h * SLEN + s] - mx);
        p_sm[h * SLEN + s] = e;
        sum += e;
    }
    #pragma unroll
    for (int off = 16; off > 0; off >>= 1)
        sum += __shfl_xor_sync(0xffffffffu, sum, off);
    float inv = 1.f / sum;
    for (int s = lane; s < SLEN; s += 32) p_sm[h * SLEN + s] *= inv;
    __syncthreads();

    {
        int sg  = lane >> 3;
        int c4  = (lane & 7) << 2;
        float4 acc4 = make_float4(0.f, 0.f, 0.f, 0.f);
        const float* ph = p_sm + h * SLEN;
        #pragma unroll 4
        for (int s = sg; s < SLEN; s += 4) {
            float p = ph[s];
            float4 v4 = *reinterpret_cast<const float4*>(vrow + (size_t)s * CH + c4);
            acc4.x = fmaf(p, v4.x, acc4.x);
            acc4.y = fmaf(p, v4.y, acc4.y);
            acc4.z = fmaf(p, v4.z, acc4.z);
            acc4.w = fmaf(p, v4.w, acc4.w);
        }
        #pragma unroll
        for (int off = 8; off <= 16; off <<= 1) {
            acc4.x += __shfl_xor_sync(0xffffffffu, acc4.x, off);
            acc4.y += __shfl_xor_sync(0xffffffffu, acc4.y, off);
            acc4.z += __shfl_xor_sync(0xffffffffu, acc4.z, off);
            acc4.w += __shfl_xor_sync(0xffffffffu, acc4.w, off);
        }
        if (sg == 0)
            *reinterpret_cast<float4*>(g_o_buf + n * HC + h * CH + c4) = acc4;
    }
}

// ---------------------------------------------------------------------------
// Kernel 4: tensor-core out_kernel (bf16x3), BM=128 tokens, 512 threads.
// 16 warps in 8x2 (16 rows x 128 cols each). A/G hi/lo in smem; W streamed.
// ---------------------------------------------------------------------------
#define A_STR   264
#define AH_OFF  0                 // 128 x 264 bf16 = 67584 B
#define AL_OFF  67584
#define BH_OFF  135168            // 16 x 264 bf16 = 8448 B
#define BL_OFF  143616
#define BG_OFF  152064
#define OV_OFF  153088
#define BO_OFF  154112
#define SMEM_BYTES 155136

__device__ __forceinline__ void gemm_bf16x3(
    char* smc, unsigned sbase,
    const __nv_bfloat16* __restrict__ WHi,
    const __nv_bfloat16* __restrict__ WLo,
    float acc[16][4], int t, int lane, int wm, int wn)
{
    for (int kk = 0; kk < 256; kk += 16) {
        {   // stream B chunk [16][256] hi+lo (512 threads, 1 uint4 each)
            int row = t >> 5;
            int c8  = (t & 31) << 3;
            *reinterpret_cast<uint4*>(smc + BH_OFF + (row * A_STR + c8) * 2) =
                *reinterpret_cast<const uint4*>(WHi + (kk + row) * 256 + c8);
            *reinterpret_cast<uint4*>(smc + BL_OFF + (row * A_STR + c8) * 2) =
                *reinterpret_cast<const uint4*>(WLo + (kk + row) * 256 + c8);
        }
        __syncthreads();

        unsigned ah[4], al[4];
        unsigned aaddr = sbase + AH_OFF +
            ((wm * 16 + (lane & 15)) * A_STR + kk + ((lane >> 4) << 3)) * 2;
        ldsm4(ah, aaddr);
        ldsm4(al, aaddr + (AL_OFF - AH_OFF));

        #pragma unroll
        for (int nb = 0; nb < 8; nb++) {
            int n0 = wn * 128 + nb * 16;
            unsigned baddr = sbase + BH_OFF +
                ((lane & 15) * A_STR + n0 + ((lane >> 4) << 3)) * 2;
            unsigned bh[4], bl[4];
            ldsm4t(bh, baddr);
            ldsm4t(bl, baddr + (BL_OFF - BH_OFF));
            mma_bf16(acc[nb * 2],     ah, bh[0], bh[1]);
            mma_bf16(acc[nb * 2],     ah, bl[0], bl[1]);
            mma_bf16(acc[nb * 2],     al, bh[0], bh[1]);
            mma_bf16(acc[nb * 2 + 1], ah, bh[2], bh[3]);
            mma_bf16(acc[nb * 2 + 1], ah, bl[2], bl[3]);
            mma_bf16(acc[nb * 2 + 1], al, bh[2], bh[3]);
        }
        __syncthreads();
    }
}

__global__ void __launch_bounds__(512)
out_kernel(const float* __restrict__ m,
           const float* __restrict__ bg,
           const float* __restrict__ bo,
           float* __restrict__ out) {
    extern __shared__ char smc[];
    unsigned sbase = (unsigned)__cvta_generic_to_shared(smc);
    float* sBG = reinterpret_cast<float*>(smc + BG_OFF);
    float* sOV = reinterpret_cast<float*>(smc + OV_OFF);
    float* sBO = reinterpret_cast<float*>(smc + BO_OFF);

    int t = threadIdx.x;
    int lane = t & 31, wid = t >> 5;
    int wm = wid >> 1, wn = wid & 1;
    int n = blockIdx.y;
    long tok0 = (long)n * SLEN + (long)blockIdx.x * 128;

    if (t < 256) {
        sBG[t] = bg[t];
        sOV[t] = g_o_buf[n * HC + t];
        sBO[t] = bo[t];
    }

    // load m tile [128][256] fp32 once, split into bf16 hi/lo smem
    #pragma unroll
    for (int i = 0; i < 16; i++) {
        int idx = t + i * 512;
        int row = idx >> 6;
        int c4  = (idx & 63) << 2;
        float4 v = *reinterpret_cast<const float4*>(m + (tok0 + row) * CIN + c4);
        split_store(smc + AH_OFF + (row * A_STR + c4) * 2,
                    smc + AL_OFF + (row * A_STR + c4) * 2, v);
    }
    __syncthreads();

    float acc[16][4];
    #pragma unroll
    for (int i = 0; i < 16; i++)
        #pragma unroll
        for (int j = 0; j < 4; j++) acc[i][j] = 0.f;

    // ---- GEMM1: M @ Wg ----
    gemm_bf16x3(smc, sbase, g_WgHi, g_WgLo, acc, t, lane, wm, wn);

    // ---- epilogue 1: G = ov * sigmoid(acc + bg), split back into Ah/Al ----
    #pragma unroll
    for (int nt = 0; nt < 16; nt++) {
        int col0 = wn * 128 + nt * 8 + (lane & 3) * 2;
        int r0   = wm * 16 + (lane >> 2);
        float bg0 = sBG[col0], bg1 = sBG[col0 + 1];
        float ov0 = sOV[col0], ov1 = sOV[col0 + 1];
        float g0 = ov0 / (1.f + __expf(-(acc[nt][0] + bg0)));
        float g1 = ov1 / (1.f + __expf(-(acc[nt][1] + bg1)));
        float g2 = ov0 / (1.f + __expf(-(acc[nt][2] + bg0)));
        float g3 = ov1 / (1.f + __expf(-(acc[nt][3] + bg1)));
        __nv_bfloat162 h01 = __floats2bfloat162_rn(g0, g1);
        __nv_bfloat162 l01 = __floats2bfloat162_rn(g0 - __low2float(h01),
                                                   g1 - __high2float(h01));
        __nv_bfloat162 h23 = __floats2bfloat162_rn(g2, g3);
        __nv_bfloat162 l23 = __floats2bfloat162_rn(g2 - __low2float(h23),
                                                   g3 - __high2float(h23));
        *reinterpret_cast<__nv_bfloat162*>(smc + AH_OFF + (r0 * A_STR + col0) * 2)       = h01;
        *reinterpret_cast<__nv_bfloat162*>(smc + AL_OFF + (r0 * A_STR + col0) * 2)       = l01;
        *reinterpret_cast<__nv_bfloat162*>(smc + AH_OFF + ((r0 + 8) * A_STR + col0) * 2) = h23;
        *reinterpret_cast<__nv_bfloat162*>(smc + AL_OFF + ((r0 + 8) * A_STR + col0) * 2) = l23;
        acc[nt][0] = acc[nt][1] = acc[nt][2] = acc[nt][3] = 0.f;
    }
    __syncthreads();

    // ---- GEMM2: G @ Wo ----
    gemm_bf16x3(smc, sbase, g_WoHi, g_WoLo, acc, t, lane, wm, wn);

    // ---- epilogue 2: + bo, write out ----
    #pragma unroll
    for (int nt = 0; nt < 16; nt++) {
        int col0 = wn * 128 + nt * 8 + (lane & 3) * 2;
        int r0   = wm * 16 + (lane >> 2);
        float2 o0 = make_float2(acc[nt][0] + sBO[col0], acc[nt][1] + sBO[col0 + 1]);
        float2 o1 = make_float2(acc[nt][2] + sBO[col0], acc[nt][3] + sBO[col0 + 1]);
        *reinterpret_cast<float2*>(out + (tok0 + r0) * CIN + col0)     = o0;
        *reinterpret_cast<float2*>(out + (tok0 + r0 + 8) * CIN + col0) = o1;
    }
}

// ---------------------------------------------------------------------------
extern "C" void kernel_launch(void* const* d_in, const int* in_sizes, int n_in,
                              void* d_out, int out_size) {
    const float* m    = (const float*)d_in[0];
    const float* mask = (const float*)d_in[1];
    const float* Wq   = (const float*)d_in[2];
    const float* Wk   = (const float*)d_in[3];
    const float* Wv   = (const float*)d_in[4];
    const float* Wg   = (const float*)d_in[5];
    const float* bg   = (const float*)d_in[6];
    const float* Wo   = (const float*)d_in[7];
    const float* bo   = (const float*)d_in[8];
    float* out = (float*)d_out;

    wconv_kernel<<<64, 256>>>(Wg, Wo, Wk, Wv);
    q_kernel<<<NROWS, 256>>>(m, mask, Wq);

    cudaFuncSetAttribute(kv_kernel,
                         cudaFuncAttributeMaxDynamicSharedMemorySize, KV_SMEM);
    kv_kernel<<<(NROWS * SLEN) / 128, 256, KV_SMEM>>>(m);

    attn_kernel<<<NROWS, 256>>>(mask);

    cudaFuncSetAttribute(out_kernel,
                         cudaFuncAttributeMaxDynamicSharedMemorySize, SMEM_BYTES);
    out_kernel<<<dim3(SLEN / 128, NROWS), 512, SMEM_BYTES>>>(m, bg, bo, out);
}

// round 7
// speedup vs baseline: 1.1458x; 1.1458x over previous
#include <cuda_runtime.h>
#include <cuda_bf16.h>
#include <math.h>

#define NROWS 384
#define SLEN  1024
#define CIN   256
#define CH    32
#define NH    8
#define HC    256   // NH*CH

// Scratch (no cudaMalloc allowed).
__device__ float g_q_buf[NROWS * HC];
__device__ float g_o_buf[NROWS * HC];
__device__ float g_k_buf[(size_t)NROWS * SLEN * CH];
__device__ float g_v_buf[(size_t)NROWS * SLEN * CH];
// Pre-split weights (bf16 hi/lo) for tensor-core paths.
__device__ __nv_bfloat16 g_WgHi[CIN * HC], g_WgLo[CIN * HC];
__device__ __nv_bfloat16 g_WoHi[HC * CIN], g_WoLo[HC * CIN];
__device__ __nv_bfloat16 g_WkvHi[CIN * 64], g_WkvLo[CIN * 64];  // Wk|Wv combined
// Masked-mean partials: [tile 0..7][n][c] and [tile][n]
__device__ float g_qpart[8 * NROWS * CIN];
__device__ float g_mpart[8 * NROWS];

// ---------------------------------------------------------------------------
// cp.async helpers
// ---------------------------------------------------------------------------
__device__ __forceinline__ void cp16(unsigned saddr, const void* g) {
    asm volatile("cp.async.cg.shared.global [%0], [%1], 16;" :: "r"(saddr), "l"(g));
}
#define CP_COMMIT() asm volatile("cp.async.commit_group;" ::: "memory")
#define CP_WAIT1()  asm volatile("cp.async.wait_group 1;" ::: "memory")
#define CP_WAIT0()  asm volatile("cp.async.wait_group 0;" ::: "memory")

// ---------------------------------------------------------------------------
// Kernel 0: split Wg, Wo, Wk|Wv into bf16 hi/lo
// ---------------------------------------------------------------------------
__global__ void wconv_kernel(const float* __restrict__ Wg,
                             const float* __restrict__ Wo,
                             const float* __restrict__ Wk,
                             const float* __restrict__ Wv) {
    int i = (blockIdx.x * 256 + threadIdx.x) * 4;  // 65536 elems per big matrix
    {
        float4 v = *reinterpret_cast<const float4*>(Wg + i);
        __nv_bfloat162 h01 = __floats2bfloat162_rn(v.x, v.y);
        __nv_bfloat162 h23 = __floats2bfloat162_rn(v.z, v.w);
        __nv_bfloat162 l01 = __floats2bfloat162_rn(v.x - __low2float(h01),
                                                   v.y - __high2float(h01));
        __nv_bfloat162 l23 = __floats2bfloat162_rn(v.z - __low2float(h23),
                                                   v.w - __high2float(h23));
        *reinterpret_cast<__nv_bfloat162*>(g_WgHi + i)     = h01;
        *reinterpret_cast<__nv_bfloat162*>(g_WgHi + i + 2) = h23;
        *reinterpret_cast<__nv_bfloat162*>(g_WgLo + i)     = l01;
        *reinterpret_cast<__nv_bfloat162*>(g_WgLo + i + 2) = l23;
    }
    {
        float4 v = *reinterpret_cast<const float4*>(Wo + i);
        __nv_bfloat162 h01 = __floats2bfloat162_rn(v.x, v.y);
        __nv_bfloat162 h23 = __floats2bfloat162_rn(v.z, v.w);
        __nv_bfloat162 l01 = __floats2bfloat162_rn(v.x - __low2float(h01),
                                                   v.y - __high2float(h01));
        __nv_bfloat162 l23 = __floats2bfloat162_rn(v.z - __low2float(h23),
                                                   v.w - __high2float(h23));
        *reinterpret_cast<__nv_bfloat162*>(g_WoHi + i)     = h01;
        *reinterpret_cast<__nv_bfloat162*>(g_WoHi + i + 2) = h23;
        *reinterpret_cast<__nv_bfloat162*>(g_WoLo + i)     = l01;
        *reinterpret_cast<__nv_bfloat162*>(g_WoLo + i + 2) = l23;
    }
    if (i < CIN * 64) {  // combined Wk|Wv: row k, col j (j<32 => Wk, else Wv)
        int k = i >> 6, j = i & 63;
        float4 v = (j < 32)
            ? *reinterpret_cast<const float4*>(Wk + k * CH + j)
            : *reinterpret_cast<const float4*>(Wv + k * CH + (j - 32));
        __nv_bfloat162 h01 = __floats2bfloat162_rn(v.x, v.y);
        __nv_bfloat162 h23 = __floats2bfloat162_rn(v.z, v.w);
        __nv_bfloat162 l01 = __floats2bfloat162_rn(v.x - __low2float(h01),
                                                   v.y - __high2float(h01));
        __nv_bfloat162 l23 = __floats2bfloat162_rn(v.z - __low2float(h23),
                                                   v.w - __high2float(h23));
        *reinterpret_cast<__nv_bfloat162*>(g_WkvHi + i)     = h01;
        *reinterpret_cast<__nv_bfloat162*>(g_WkvHi + i + 2) = h23;
        *reinterpret_cast<__nv_bfloat162*>(g_WkvLo + i)     = l01;
        *reinterpret_cast<__nv_bfloat162*>(g_WkvLo + i + 2) = l23;
    }
}

// ---------------------------------------------------------------------------
// MMA helpers (bf16x3 split)
// ---------------------------------------------------------------------------
__device__ __forceinline__ void ldsm4(unsigned r[4], unsigned addr) {
    asm volatile("ldmatrix.sync.aligned.m8n8.x4.shared.b16 {%0,%1,%2,%3}, [%4];"
        : "=r"(r[0]), "=r"(r[1]), "=r"(r[2]), "=r"(r[3]) : "r"(addr));
}
__device__ __forceinline__ void ldsm4t(unsigned r[4], unsigned addr) {
    asm volatile("ldmatrix.sync.aligned.m8n8.x4.trans.shared.b16 {%0,%1,%2,%3}, [%4];"
        : "=r"(r[0]), "=r"(r[1]), "=r"(r[2]), "=r"(r[3]) : "r"(addr));
}
__device__ __forceinline__ void mma_bf16(float c[4], const unsigned a[4],
                                         unsigned b0, unsigned b1) {
    asm volatile("mma.sync.aligned.m16n8k16.row.col.f32.bf16.bf16.f32 "
        "{%0,%1,%2,%3}, {%4,%5,%6,%7}, {%8,%9}, {%0,%1,%2,%3};"
        : "+f"(c[0]), "+f"(c[1]), "+f"(c[2]), "+f"(c[3])
        : "r"(a[0]), "r"(a[1]), "r"(a[2]), "r"(a[3]), "r"(b0), "r"(b1));
}

__device__ __forceinline__ void split_store(char* ph, char* pl, float4 v) {
    __nv_bfloat162 h01 = __floats2bfloat162_rn(v.x, v.y);
    __nv_bfloat162 h23 = __floats2bfloat162_rn(v.z, v.w);
    __nv_bfloat162 l01 = __floats2bfloat162_rn(v.x - __low2float(h01),
                                               v.y - __high2float(h01));
    __nv_bfloat162 l23 = __floats2bfloat162_rn(v.z - __low2float(h23),
                                               v.w - __high2float(h23));
    reinterpret_cast<__nv_bfloat162*>(ph)[0] = h01;
    reinterpret_cast<__nv_bfloat162*>(ph)[1] = h23;
    reinterpret_cast<__nv_bfloat162*>(pl)[0] = l01;
    reinterpret_cast<__nv_bfloat162*>(pl)[1] = l23;
}

// ---------------------------------------------------------------------------
// Kernel 2: k|v = m @ (Wk|Wv), bf16x3 tensor path + fused masked-mean partials.
// CTA = 128 tokens (row n = blockIdx>>3, tile = blockIdx&7), 256 threads.
// cp.async double-buffered weight chunks.
// ---------------------------------------------------------------------------
#define KA_STR  264
#define KAH_OFF 0                 // 128 x 264 bf16 = 67584 B
#define KAL_OFF 67584
#define KB_STR  72
#define KB0_OFF 135168            // stage s at KB0 + s*4608; hi then lo (+2304)
#define KV_SMEM 144384

__device__ __forceinline__ void kv_prefetch(unsigned sbase, int stage, int kk, int t) {
    int f = t & 127;
    int row = f >> 3, c8 = (f & 7) << 3;
    unsigned dst = sbase + KB0_OFF + stage * 4608 + ((t < 128) ? 0 : 2304)
                 + (row * KB_STR + c8) * 2;
    const __nv_bfloat16* src = ((t < 128) ? g_WkvHi : g_WkvLo) + (kk + row) * 64 + c8;
    cp16(dst, src);
}

__global__ void __launch_bounds__(256)
kv_kernel(const float* __restrict__ m, const float* __restrict__ mask) {
    extern __shared__ char smc[];
    __shared__ float mask_sm[128];
    unsigned sbase = (unsigned)__cvta_generic_to_shared(smc);
    int t = threadIdx.x;
    int lane = t & 31, wm = t >> 5;
    int n    = blockIdx.x >> 3;
    int tile = blockIdx.x & 7;
    long r0g = (long)blockIdx.x * 128;

    if (t < 128) mask_sm[t] = mask[(size_t)n * SLEN + tile * 128 + t];

    // load m tile [128][256] fp32, split into hi/lo smem
    #pragma unroll
    for (int i = 0; i < 32; i++) {
        int idx = t + i * 256;
        int row = idx >> 6;
        int c4  = (idx & 63) << 2;
        float4 v = *reinterpret_cast<const float4*>(m + (r0g + row) * CIN + c4);
        split_store(smc + KAH_OFF + (row * KA_STR + c4) * 2,
                    smc + KAL_OFF + (row * KA_STR + c4) * 2, v);
    }
    __syncthreads();

    // prefetch weight chunk 0 while computing mean partials
    kv_prefetch(sbase, 0, 0, t);
    CP_COMMIT();

    // masked-mean partial for channel t over this CTA's 128 tokens
    {
        float qs = 0.f;
        #pragma unroll 8
        for (int r = 0; r < 128; r++) {
            float hi = __bfloat162float(*reinterpret_cast<__nv_bfloat16*>(
                smc + KAH_OFF + (r * KA_STR + t) * 2));
            float lo = __bfloat162float(*reinterpret_cast<__nv_bfloat16*>(
                smc + KAL_OFF + (r * KA_STR + t) * 2));
            qs = fmaf(hi + lo, mask_sm[r], qs);
        }
        g_qpart[(tile * NROWS + n) * CIN + t] = qs;
        if (t == 0) {
            float ms = 0.f;
            for (int r = 0; r < 128; r++) ms += mask_sm[r];
            g_mpart[tile * NROWS + n] = ms;
        }
    }

    float acc[8][4];
    #pragma unroll
    for (int i = 0; i < 8; i++)
        #pragma unroll
        for (int j = 0; j < 4; j++) acc[i][j] = 0.f;

    for (int c = 0; c < 16; c++) {
        if (c < 15) { kv_prefetch(sbase, (c + 1) & 1, (c + 1) * 16, t); CP_COMMIT(); CP_WAIT1(); }
        else        { CP_WAIT0(); }
        __syncthreads();
        int kk = c * 16, s = c & 1;
        unsigned kbh = sbase + KB0_OFF + s * 4608;

        unsigned ah[4], al[4];
        unsigned aaddr = sbase + KAH_OFF +
            ((wm * 16 + (lane & 15)) * KA_STR + kk + ((lane >> 4) << 3)) * 2;
        ldsm4(ah, aaddr);
        ldsm4(al, aaddr + KAL_OFF);

        #pragma unroll
        for (int nb = 0; nb < 4; nb++) {
            unsigned baddr = kbh +
                ((lane & 15) * KB_STR + nb * 16 + ((lane >> 4) << 3)) * 2;
            unsigned bh[4], bl[4];
            ldsm4t(bh, baddr);
            ldsm4t(bl, baddr + 2304);
            mma_bf16(acc[nb * 2],     ah, bh[0], bh[1]);
            mma_bf16(acc[nb * 2],     ah, bl[0], bl[1]);
            mma_bf16(acc[nb * 2],     al, bh[0], bh[1]);
            mma_bf16(acc[nb * 2 + 1], ah, bh[2], bh[3]);
            mma_bf16(acc[nb * 2 + 1], ah, bl[2], bl[3]);
            mma_bf16(acc[nb * 2 + 1], al, bh[2], bh[3]);
        }
        __syncthreads();
    }

    // write k (cols 0..31) and v (cols 32..63)
    #pragma unroll
    for (int nb = 0; nb < 4; nb++) {
        #pragma unroll
        for (int half = 0; half < 2; half++) {
            int col = nb * 16 + half * 8 + (lane & 3) * 2;
            int r0  = wm * 16 + (lane >> 2);
            float* f = acc[nb * 2 + half];
            float* dst = (col < CH) ? (g_k_buf + ((r0g + r0) * CH + col))
                                    : (g_v_buf + ((r0g + r0) * CH + col - CH));
            *reinterpret_cast<float2*>(dst) = make_float2(f[0], f[1]);
            dst += 8 * CH;
            *reinterpret_cast<float2*>(dst) = make_float2(f[2], f[3]);
        }
    }
}

// ---------------------------------------------------------------------------
// Kernel 2b: finish mean + q = (mean @ Wq) * C^-0.5   (tiny)
// ---------------------------------------------------------------------------
__global__ void q2_kernel(const float* __restrict__ Wq) {
    int n = blockIdx.x, t = threadIdx.x;
    __shared__ float qm[CIN];
    float s = 0.f;
    #pragma unroll
    for (int p = 0; p < 8; p++) s += g_qpart[(p * NROWS + n) * CIN + t];
    float mk = 0.f;
    #pragma unroll
    for (int p = 0; p < 8; p++) mk += g_mpart[p * NROWS + n];
    qm[t] = s / (mk + 1e-10f);
    __syncthreads();
    float acc = 0.f;
    #pragma unroll 8
    for (int c = 0; c < CIN; c++) acc = fmaf(qm[c], Wq[c * HC + t], acc);
    g_q_buf[n * HC + t] = acc * 0.17677669529663687f;
}

// ---------------------------------------------------------------------------
// Kernel 3: attention (logits + softmax + p@v), fp32
// ---------------------------------------------------------------------------
__global__ void __launch_bounds__(256, 2)
attn_kernel(const float* __restrict__ mask) {
    int n = blockIdx.x, t = threadIdx.x;
    __shared__ float q_sm[HC];
    __shared__ float p_sm[NH * SLEN];

    q_sm[t] = g_q_buf[n * HC + t];
    __syncthreads();

    const float* krow = g_k_buf + (size_t)n * SLEN * CH;
    const float* vrow = g_v_buf + (size_t)n * SLEN * CH;
    const float* mk   = mask + (size_t)n * SLEN;

    for (int s = t; s < SLEN; s += 256) {
        float kreg[32];
        #pragma unroll
        for (int q = 0; q < 8; q++)
            *reinterpret_cast<float4*>(kreg + q * 4) =
                *reinterpret_cast<const float4*>(krow + (size_t)s * CH + q * 4);
        float bias = 1e9f * (mk[s] - 1.0f);
        #pragma unroll
        for (int h = 0; h < NH; h++) {
            float d = 0.f;
            #pragma unroll
            for (int j = 0; j < 32; j++) d = fmaf(q_sm[h * 32 + j], kreg[j], d);
            p_sm[h * SLEN + s] = d + bias;
        }
    }
    __syncthreads();

    int h = t >> 5, lane = t & 31;
    float mx = -3.0e38f;
    for (int s = lane; s < SLEN; s += 32) mx = fmaxf(mx, p_sm[h * SLEN + s]);
    #pragma unroll
    for (int off = 16; off > 0; off >>= 1)
        mx = fmaxf(mx, __shfl_xor_sync(0xffffffffu, mx, off));

    float sum = 0.f;
    for (int s = lane; s < SLEN; s += 32) {
        float e = __expf(p_sm[h * SLEN + s] - mx);
        p_sm[h * SLEN + s] = e;
        sum += e;
    }
    #pragma unroll
    for (int off = 16; off > 0; off >>= 1)
        sum += __shfl_xor_sync(0xffffffffu, sum, off);
    float inv = 1.f / sum;
    for (int s = lane; s < SLEN; s += 32) p_sm[h * SLEN + s] *= inv;
    __syncthreads();

    {
        int sg  = lane >> 3;
        int c4  = (lane & 7) << 2;
        float4 acc4 = make_float4(0.f, 0.f, 0.f, 0.f);
        const float* ph = p_sm + h * SLEN;
        #pragma unroll 4
        for (int s = sg; s < SLEN; s += 4) {
            float p = ph[s];
            float4 v4 = *reinterpret_cast<const float4*>(vrow + (size_t)s * CH + c4);
            acc4.x = fmaf(p, v4.x, acc4.x);
            acc4.y = fmaf(p, v4.y, acc4.y);
            acc4.z = fmaf(p, v4.z, acc4.z);
            acc4.w = fmaf(p, v4.w, acc4.w);
        }
        #pragma unroll
        for (int off = 8; off <= 16; off <<= 1) {
            acc4.x += __shfl_xor_sync(0xffffffffu, acc4.x, off);
            acc4.y += __shfl_xor_sync(0xffffffffu, acc4.y, off);
            acc4.z += __shfl_xor_sync(0xffffffffu, acc4.z, off);
            acc4.w += __shfl_xor_sync(0xffffffffu, acc4.w, off);
        }
        if (sg == 0)
            *reinterpret_cast<float4*>(g_o_buf + n * HC + h * CH + c4) = acc4;
    }
}

// ---------------------------------------------------------------------------
// Kernel 4: tensor-core out_kernel (bf16x3), BM=64, 256 threads, 2 CTAs/SM,
// cp.async double-buffered weight chunks.
// ---------------------------------------------------------------------------
#define A_STR   264
#define AH_OFF  0                 // 64 x 264 bf16 = 33792 B
#define AL_OFF  33792
#define B0_OFF  67584             // stage s at B0 + s*16896; hi then lo (+8448)
#define BG_OFF  101376
#define OV_OFF  102400
#define BO_OFF  103424
#define SMEM_BYTES 104448

__device__ __forceinline__ void out_prefetch(unsigned sbase, int stage,
        const __nv_bfloat16* __restrict__ WHi,
        const __nv_bfloat16* __restrict__ WLo, int kk, int t) {
    unsigned bh = sbase + B0_OFF + stage * 16896;
    #pragma unroll
    for (int i = 0; i < 2; i++) {
        int f = t + i * 256;
        int row = f >> 5, c8 = (f & 31) << 3;
        unsigned off = (row * A_STR + c8) * 2;
        cp16(bh + off,        WHi + (kk + row) * 256 + c8);
        cp16(bh + 8448 + off, WLo + (kk + row) * 256 + c8);
    }
}

__device__ __forceinline__ void gemm_bf16x3(
    unsigned sbase,
    const __nv_bfloat16* __restrict__ WHi,
    const __nv_bfloat16* __restrict__ WLo,
    float acc[16][4], int t, int lane, int wm, int wn)
{
    out_prefetch(sbase, 0, WHi, WLo, 0, t);
    CP_COMMIT();
    for (int c = 0; c < 16; c++) {
        if (c < 15) { out_prefetch(sbase, (c + 1) & 1, WHi, WLo, (c + 1) * 16, t);
                      CP_COMMIT(); CP_WAIT1(); }
        else        { CP_WAIT0(); }
        __syncthreads();
        int kk = c * 16, s = c & 1;
        unsigned bhb = sbase + B0_OFF + s * 16896;

        unsigned ah[4], al[4];
        unsigned aaddr = sbase + AH_OFF +
            ((wm * 16 + (lane & 15)) * A_STR + kk + ((lane >> 4) << 3)) * 2;
        ldsm4(ah, aaddr);
        ldsm4(al, aaddr + AL_OFF);

        #pragma unroll
        for (int nb = 0; nb < 8; nb++) {
            int n0 = wn * 128 + nb * 16;
            unsigned baddr = bhb +
                ((lane & 15) * A_STR + n0 + ((lane >> 4) << 3)) * 2;
            unsigned bh4[4], bl4[4];
            ldsm4t(bh4, baddr);
            ldsm4t(bl4, baddr + 8448);
            mma_bf16(acc[nb * 2],     ah, bh4[0], bh4[1]);
            mma_bf16(acc[nb * 2],     ah, bl4[0], bl4[1]);
            mma_bf16(acc[nb * 2],     al, bh4[0], bh4[1]);
            mma_bf16(acc[nb * 2 + 1], ah, bh4[2], bh4[3]);
            mma_bf16(acc[nb * 2 + 1], ah, bl4[2], bl4[3]);
            mma_bf16(acc[nb * 2 + 1], al, bh4[2], bh4[3]);
        }
        __syncthreads();
    }
}

__global__ void __launch_bounds__(256, 2)
out_kernel(const float* __restrict__ m,
           const float* __restrict__ bg,
           const float* __restrict__ bo,
           float* __restrict__ out) {
    extern __shared__ char smc[];
    unsigned sbase = (unsigned)__cvta_generic_to_shared(smc);
    float* sBG = reinterpret_cast<float*>(smc + BG_OFF);
    float* sOV = reinterpret_cast<float*>(smc + OV_OFF);
    float* sBO = reinterpret_cast<float*>(smc + BO_OFF);

    int t = threadIdx.x;
    int lane = t & 31, wid = t >> 5;
    int wm = wid >> 1, wn = wid & 1;
    int n = blockIdx.y;
    long tok0 = (long)n * SLEN + (long)blockIdx.x * 64;

    sBG[t] = bg[t];
    sOV[t] = g_o_buf[n * HC + t];
    sBO[t] = bo[t];

    // load m tile [64][256] fp32 once, split into bf16 hi/lo smem
    #pragma unroll
    for (int i = 0; i < 16; i++) {
        int idx = t + i * 256;
        int row = idx >> 6;
        int c4  = (idx & 63) << 2;
        float4 v = *reinterpret_cast<const float4*>(m + (tok0 + row) * CIN + c4);
        split_store(smc + AH_OFF + (row * A_STR + c4) * 2,
                    smc + AL_OFF + (row * A_STR + c4) * 2, v);
    }
    __syncthreads();

    float acc[16][4];
    #pragma unroll
    for (int i = 0; i < 16; i++)
        #pragma unroll
        for (int j = 0; j < 4; j++) acc[i][j] = 0.f;

    // ---- GEMM1: M @ Wg ----
    gemm_bf16x3(sbase, g_WgHi, g_WgLo, acc, t, lane, wm, wn);

    // ---- epilogue 1: G = ov * sigmoid(acc + bg), split back into Ah/Al ----
    #pragma unroll
    for (int nt = 0; nt < 16; nt++) {
        int col0 = wn * 128 + nt * 8 + (lane & 3) * 2;
        int r0   = wm * 16 + (lane >> 2);
        float bg0 = sBG[col0], bg1 = sBG[col0 + 1];
        float ov0 = sOV[col0], ov1 = sOV[col0 + 1];
        float g0 = ov0 / (1.f + __expf(-(acc[nt][0] + bg0)));
        float g1 = ov1 / (1.f + __expf(-(acc[nt][1] + bg1)));
        float g2 = ov0 / (1.f + __expf(-(acc[nt][2] + bg0)));
        float g3 = ov1 / (1.f + __expf(-(acc[nt][3] + bg1)));
        __nv_bfloat162 h01 = __floats2bfloat162_rn(g0, g1);
        __nv_bfloat162 l01 = __floats2bfloat162_rn(g0 - __low2float(h01),
                                                   g1 - __high2float(h01));
        __nv_bfloat162 h23 = __floats2bfloat162_rn(g2, g3);
        __nv_bfloat162 l23 = __floats2bfloat162_rn(g2 - __low2float(h23),
                                                   g3 - __high2float(h23));
        *reinterpret_cast<__nv_bfloat162*>(smc + AH_OFF + (r0 * A_STR + col0) * 2)       = h01;
        *reinterpret_cast<__nv_bfloat162*>(smc + AL_OFF + (r0 * A_STR + col0) * 2)       = l01;
        *reinterpret_cast<__nv_bfloat162*>(smc + AH_OFF + ((r0 + 8) * A_STR + col0) * 2) = h23;
        *reinterpret_cast<__nv_bfloat162*>(smc + AL_OFF + ((r0 + 8) * A_STR + col0) * 2) = l23;
        acc[nt][0] = acc[nt][1] = acc[nt][2] = acc[nt][3] = 0.f;
    }
    __syncthreads();

    // ---- GEMM2: G @ Wo ----
    gemm_bf16x3(sbase, g_WoHi, g_WoLo, acc, t, lane, wm, wn);

    // ---- epilogue 2: + bo, write out ----
    #pragma unroll
    for (int nt = 0; nt < 16; nt++) {
        int col0 = wn * 128 + nt * 8 + (lane & 3) * 2;
        int r0   = wm * 16 + (lane >> 2);
        float2 o0 = make_float2(acc[nt][0] + sBO[col0], acc[nt][1] + sBO[col0 + 1]);
        float2 o1 = make_float2(acc[nt][2] + sBO[col0], acc[nt][3] + sBO[col0 + 1]);
        *reinterpret_cast<float2*>(out + (tok0 + r0) * CIN + col0)     = o0;
        *reinterpret_cast<float2*>(out + (tok0 + r0 + 8) * CIN + col0) = o1;
    }
}

// ---------------------------------------------------------------------------
extern "C" void kernel_launch(void* const* d_in, const int* in_sizes, int n_in,
                              void* d_out, int out_size) {
    const float* m    = (const float*)d_in[0];
    const float* mask = (const float*)d_in[1];
    const float* Wq   = (const float*)d_in[2];
    const float* Wk   = (const float*)d_in[3];
    const float* Wv   = (const float*)d_in[4];
    const float* Wg   = (const float*)d_in[5];
    const float* bg   = (const float*)d_in[6];
    const float* Wo   = (const float*)d_in[7];
    const float* bo   = (const float*)d_in[8];
    float* out = (float*)d_out;

    wconv_kernel<<<64, 256>>>(Wg, Wo, Wk, Wv);

    cudaFuncSetAttribute(kv_kernel,
                         cudaFuncAttributeMaxDynamicSharedMemorySize, KV_SMEM);
    kv_kernel<<<(NROWS * SLEN) / 128, 256, KV_SMEM>>>(m, mask);

    q2_kernel<<<NROWS, 256>>>(Wq);

    attn_kernel<<<NROWS, 256>>>(mask);

    cudaFuncSetAttribute(out_kernel,
                         cudaFuncAttributeMaxDynamicSharedMemorySize, SMEM_BYTES);
    out_kernel<<<dim3(SLEN / 64, NROWS), 256, SMEM_BYTES>>>(m, bg, bo, out);
}

// round 8
// speedup vs baseline: 1.1471x; 1.0011x over previous
#include <cuda_runtime.h>
#include <cuda_bf16.h>
#include <math.h>

#define NROWS 384
#define SLEN  1024
#define CIN   256
#define CH    32
#define NH    8
#define HC    256   // NH*CH

// Scratch (no cudaMalloc allowed).
__device__ float g_q_buf[NROWS * HC];
__device__ float g_o_buf[NROWS * HC];
__device__ float g_k_buf[(size_t)NROWS * SLEN * CH];
__device__ float g_v_buf[(size_t)NROWS * SLEN * CH];
// Pre-split weights (bf16 hi/lo) for tensor-core paths.
__device__ __nv_bfloat16 g_WgHi[CIN * HC], g_WgLo[CIN * HC];
__device__ __nv_bfloat16 g_WoHi[HC * CIN], g_WoLo[HC * CIN];
__device__ __nv_bfloat16 g_WkvHi[CIN * 64], g_WkvLo[CIN * 64];  // Wk|Wv combined
// Masked-mean partials: [tile 0..7][n][c] and [tile][n]
__device__ float g_qpart[8 * NROWS * CIN];
__device__ float g_mpart[8 * NROWS];

// ---------------------------------------------------------------------------
// cp.async helpers
// ---------------------------------------------------------------------------
__device__ __forceinline__ void cp16(unsigned saddr, const void* g) {
    asm volatile("cp.async.cg.shared.global [%0], [%1], 16;" :: "r"(saddr), "l"(g));
}
#define CP_COMMIT() asm volatile("cp.async.commit_group;" ::: "memory")
#define CP_WAIT1()  asm volatile("cp.async.wait_group 1;" ::: "memory")
#define CP_WAIT0()  asm volatile("cp.async.wait_group 0;" ::: "memory")

// ---------------------------------------------------------------------------
// Kernel 0: split Wg, Wo, Wk|Wv into bf16 hi/lo
// ---------------------------------------------------------------------------
__global__ void wconv_kernel(const float* __restrict__ Wg,
                             const float* __restrict__ Wo,
                             const float* __restrict__ Wk,
                             const float* __restrict__ Wv) {
    int i = (blockIdx.x * 256 + threadIdx.x) * 4;  // 65536 elems per big matrix
    {
        float4 v = *reinterpret_cast<const float4*>(Wg + i);
        __nv_bfloat162 h01 = __floats2bfloat162_rn(v.x, v.y);
        __nv_bfloat162 h23 = __floats2bfloat162_rn(v.z, v.w);
        __nv_bfloat162 l01 = __floats2bfloat162_rn(v.x - __low2float(h01),
                                                   v.y - __high2float(h01));
        __nv_bfloat162 l23 = __floats2bfloat162_rn(v.z - __low2float(h23),
                                                   v.w - __high2float(h23));
        *reinterpret_cast<__nv_bfloat162*>(g_WgHi + i)     = h01;
        *reinterpret_cast<__nv_bfloat162*>(g_WgHi + i + 2) = h23;
        *reinterpret_cast<__nv_bfloat162*>(g_WgLo + i)     = l01;
        *reinterpret_cast<__nv_bfloat162*>(g_WgLo + i + 2) = l23;
    }
    {
        float4 v = *reinterpret_cast<const float4*>(Wo + i);
        __nv_bfloat162 h01 = __floats2bfloat162_rn(v.x, v.y);
        __nv_bfloat162 h23 = __floats2bfloat162_rn(v.z, v.w);
        __nv_bfloat162 l01 = __floats2bfloat162_rn(v.x - __low2float(h01),
                                                   v.y - __high2float(h01));
        __nv_bfloat162 l23 = __floats2bfloat162_rn(v.z - __low2float(h23),
                                                   v.w - __high2float(h23));
        *reinterpret_cast<__nv_bfloat162*>(g_WoHi + i)     = h01;
        *reinterpret_cast<__nv_bfloat162*>(g_WoHi + i + 2) = h23;
        *reinterpret_cast<__nv_bfloat162*>(g_WoLo + i)     = l01;
        *reinterpret_cast<__nv_bfloat162*>(g_WoLo + i + 2) = l23;
    }
    if (i < CIN * 64) {  // combined Wk|Wv: row k, col j (j<32 => Wk, else Wv)
        int k = i >> 6, j = i & 63;
        float4 v = (j < 32)
            ? *reinterpret_cast<const float4*>(Wk + k * CH + j)
            : *reinterpret_cast<const float4*>(Wv + k * CH + (j - 32));
        __nv_bfloat162 h01 = __floats2bfloat162_rn(v.x, v.y);
        __nv_bfloat162 h23 = __floats2bfloat162_rn(v.z, v.w);
        __nv_bfloat162 l01 = __floats2bfloat162_rn(v.x - __low2float(h01),
                                                   v.y - __high2float(h01));
        __nv_bfloat162 l23 = __floats2bfloat162_rn(v.z - __low2float(h23),
                                                   v.w - __high2float(h23));
        *reinterpret_cast<__nv_bfloat162*>(g_WkvHi + i)     = h01;
        *reinterpret_cast<__nv_bfloat162*>(g_WkvHi + i + 2) = h23;
        *reinterpret_cast<__nv_bfloat162*>(g_WkvLo + i)     = l01;
        *reinterpret_cast<__nv_bfloat162*>(g_WkvLo + i + 2) = l23;
    }
}

// ---------------------------------------------------------------------------
// MMA helpers (bf16x3 split)
// ---------------------------------------------------------------------------
__device__ __forceinline__ void ldsm4(unsigned r[4], unsigned addr) {
    asm volatile("ldmatrix.sync.aligned.m8n8.x4.shared.b16 {%0,%1,%2,%3}, [%4];"
        : "=r"(r[0]), "=r"(r[1]), "=r"(r[2]), "=r"(r[3]) : "r"(addr));
}
__device__ __forceinline__ void ldsm4t(unsigned r[4], unsigned addr) {
    asm volatile("ldmatrix.sync.aligned.m8n8.x4.trans.shared.b16 {%0,%1,%2,%3}, [%4];"
        : "=r"(r[0]), "=r"(r[1]), "=r"(r[2]), "=r"(r[3]) : "r"(addr));
}
__device__ __forceinline__ void mma_bf16(float c[4], const unsigned a[4],
                                         unsigned b0, unsigned b1) {
    asm volatile("mma.sync.aligned.m16n8k16.row.col.f32.bf16.bf16.f32 "
        "{%0,%1,%2,%3}, {%4,%5,%6,%7}, {%8,%9}, {%0,%1,%2,%3};"
        : "+f"(c[0]), "+f"(c[1]), "+f"(c[2]), "+f"(c[3])
        : "r"(a[0]), "r"(a[1]), "r"(a[2]), "r"(a[3]), "r"(b0), "r"(b1));
}

__device__ __forceinline__ void split_store(char* ph, char* pl, float4 v) {
    __nv_bfloat162 h01 = __floats2bfloat162_rn(v.x, v.y);
    __nv_bfloat162 h23 = __floats2bfloat162_rn(v.z, v.w);
    __nv_bfloat162 l01 = __floats2bfloat162_rn(v.x - __low2float(h01),
                                               v.y - __high2float(h01));
    __nv_bfloat162 l23 = __floats2bfloat162_rn(v.z - __low2float(h23),
                                               v.w - __high2float(h23));
    reinterpret_cast<__nv_bfloat162*>(ph)[0] = h01;
    reinterpret_cast<__nv_bfloat162*>(ph)[1] = h23;
    reinterpret_cast<__nv_bfloat162*>(pl)[0] = l01;
    reinterpret_cast<__nv_bfloat162*>(pl)[1] = l23;
}

// ---------------------------------------------------------------------------
// Kernel 2: k|v = m @ (Wk|Wv), bf16x3 tensor path + fused masked-mean partials.
// CTA = 128 tokens (row n = blockIdx>>3, tile = blockIdx&7), 256 threads.
// cp.async double-buffered weight chunks.
// ---------------------------------------------------------------------------
#define KA_STR  264
#define KAH_OFF 0                 // 128 x 264 bf16 = 67584 B
#define KAL_OFF 67584
#define KB_STR  72
#define KB0_OFF 135168            // stage s at KB0 + s*4608; hi then lo (+2304)
#define KV_SMEM 144384

__device__ __forceinline__ void kv_prefetch(unsigned sbase, int stage, int kk, int t) {
    int f = t & 127;
    int row = f >> 3, c8 = (f & 7) << 3;
    unsigned dst = sbase + KB0_OFF + stage * 4608 + ((t < 128) ? 0 : 2304)
                 + (row * KB_STR + c8) * 2;
    const __nv_bfloat16* src = ((t < 128) ? g_WkvHi : g_WkvLo) + (kk + row) * 64 + c8;
    cp16(dst, src);
}

__global__ void __launch_bounds__(256)
kv_kernel(const float* __restrict__ m, const float* __restrict__ mask) {
    extern __shared__ char smc[];
    __shared__ float mask_sm[128];
    unsigned sbase = (unsigned)__cvta_generic_to_shared(smc);
    int t = threadIdx.x;
    int lane = t & 31, wm = t >> 5;
    int n    = blockIdx.x >> 3;
    int tile = blockIdx.x & 7;
    long r0g = (long)blockIdx.x * 128;

    if (t < 128) mask_sm[t] = mask[(size_t)n * SLEN + tile * 128 + t];

    // load m tile [128][256] fp32, split into hi/lo smem
    #pragma unroll
    for (int i = 0; i < 32; i++) {
        int idx = t + i * 256;
        int row = idx >> 6;
        int c4  = (idx & 63) << 2;
        float4 v = *reinterpret_cast<const float4*>(m + (r0g + row) * CIN + c4);
        split_store(smc + KAH_OFF + (row * KA_STR + c4) * 2,
                    smc + KAL_OFF + (row * KA_STR + c4) * 2, v);
    }
    __syncthreads();

    // prefetch weight chunk 0 while computing mean partials
    kv_prefetch(sbase, 0, 0, t);
    CP_COMMIT();

    // masked-mean partial for channel t over this CTA's 128 tokens
    {
        float qs = 0.f;
        #pragma unroll 8
        for (int r = 0; r < 128; r++) {
            float hi = __bfloat162float(*reinterpret_cast<__nv_bfloat16*>(
                smc + KAH_OFF + (r * KA_STR + t) * 2));
            float lo = __bfloat162float(*reinterpret_cast<__nv_bfloat16*>(
                smc + KAL_OFF + (r * KA_STR + t) * 2));
            qs = fmaf(hi + lo, mask_sm[r], qs);
        }
        g_qpart[(tile * NROWS + n) * CIN + t] = qs;
        if (t == 0) {
            float ms = 0.f;
            for (int r = 0; r < 128; r++) ms += mask_sm[r];
            g_mpart[tile * NROWS + n] = ms;
        }
    }

    float acc[8][4];
    #pragma unroll
    for (int i = 0; i < 8; i++)
        #pragma unroll
        for (int j = 0; j < 4; j++) acc[i][j] = 0.f;

    for (int c = 0; c < 16; c++) {
        if (c < 15) { kv_prefetch(sbase, (c + 1) & 1, (c + 1) * 16, t); CP_COMMIT(); CP_WAIT1(); }
        else        { CP_WAIT0(); }
        __syncthreads();
        int kk = c * 16, s = c & 1;
        unsigned kbh = sbase + KB0_OFF + s * 4608;

        unsigned ah[4], al[4];
        unsigned aaddr = sbase + KAH_OFF +
            ((wm * 16 + (lane & 15)) * KA_STR + kk + ((lane >> 4) << 3)) * 2;
        ldsm4(ah, aaddr);
        ldsm4(al, aaddr + KAL_OFF);

        #pragma unroll
        for (int nb = 0; nb < 4; nb++) {
            unsigned baddr = kbh +
                ((lane & 15) * KB_STR + nb * 16 + ((lane >> 4) << 3)) * 2;
            unsigned bh[4], bl[4];
            ldsm4t(bh, baddr);
            ldsm4t(bl, baddr + 2304);
            mma_bf16(acc[nb * 2],     ah, bh[0], bh[1]);
            mma_bf16(acc[nb * 2],     ah, bl[0], bl[1]);
            mma_bf16(acc[nb * 2],     al, bh[0], bh[1]);
            mma_bf16(acc[nb * 2 + 1], ah, bh[2], bh[3]);
            mma_bf16(acc[nb * 2 + 1], ah, bl[2], bl[3]);
            mma_bf16(acc[nb * 2 + 1], al, bh[2], bh[3]);
        }
        __syncthreads();
    }

    // write k (cols 0..31) and v (cols 32..63)
    #pragma unroll
    for (int nb = 0; nb < 4; nb++) {
        #pragma unroll
        for (int half = 0; half < 2; half++) {
            int col = nb * 16 + half * 8 + (lane & 3) * 2;
            int r0  = wm * 16 + (lane >> 2);
            float* f = acc[nb * 2 + half];
            float* dst = (col < CH) ? (g_k_buf + ((r0g + r0) * CH + col))
                                    : (g_v_buf + ((r0g + r0) * CH + col - CH));
            *reinterpret_cast<float2*>(dst) = make_float2(f[0], f[1]);
            dst += 8 * CH;
            *reinterpret_cast<float2*>(dst) = make_float2(f[2], f[3]);
        }
    }
}

// ---------------------------------------------------------------------------
// Kernel 2b: finish mean + q = (mean @ Wq) * C^-0.5   (tiny)
// ---------------------------------------------------------------------------
__global__ void q2_kernel(const float* __restrict__ Wq) {
    int n = blockIdx.x, t = threadIdx.x;
    __shared__ float qm[CIN];
    float s = 0.f;
    #pragma unroll
    for (int p = 0; p < 8; p++) s += g_qpart[(p * NROWS + n) * CIN + t];
    float mk = 0.f;
    #pragma unroll
    for (int p = 0; p < 8; p++) mk += g_mpart[p * NROWS + n];
    qm[t] = s / (mk + 1e-10f);
    __syncthreads();
    float acc = 0.f;
    #pragma unroll 8
    for (int c = 0; c < CIN; c++) acc = fmaf(qm[c], Wq[c * HC + t], acc);
    g_q_buf[n * HC + t] = acc * 0.17677669529663687f;
}

// ---------------------------------------------------------------------------
// Kernel 3: attention (logits + softmax + p@v), fp32
// ---------------------------------------------------------------------------
__global__ void __launch_bounds__(256, 2)
attn_kernel(const float* __restrict__ mask) {
    int n = blockIdx.x, t = threadIdx.x;
    __shared__ float q_sm[HC];
    __shared__ float p_sm[NH * SLEN];

    q_sm[t] = g_q_buf[n * HC + t];
    __syncthreads();

    const float* krow = g_k_buf + (size_t)n * SLEN * CH;
    const float* vrow = g_v_buf + (size_t)n * SLEN * CH;
    const float* mk   = mask + (size_t)n * SLEN;

    for (int s = t; s < SLEN; s += 256) {
        float kreg[32];
        #pragma unroll
        for (int q = 0; q < 8; q++)
            *reinterpret_cast<float4*>(kreg + q * 4) =
                *reinterpret_cast<const float4*>(krow + (size_t)s * CH + q * 4);
        float bias = 1e9f * (mk[s] - 1.0f);
        #pragma unroll
        for (int h = 0; h < NH; h++) {
            float d = 0.f;
            #pragma unroll
            for (int j = 0; j < 32; j++) d = fmaf(q_sm[h * 32 + j], kreg[j], d);
            p_sm[h * SLEN + s] = d + bias;
        }
    }
    __syncthreads();

    int h = t >> 5, lane = t & 31;
    float mx = -3.0e38f;
    for (int s = lane; s < SLEN; s += 32) mx = fmaxf(mx, p_sm[h * SLEN + s]);
    #pragma unroll
    for (int off = 16; off > 0; off >>= 1)
        mx = fmaxf(mx, __shfl_xor_sync(0xffffffffu, mx, off));

    float sum = 0.f;
    for (int s = lane; s < SLEN; s += 32) {
        float e = __expf(p_sm[h * SLEN + s] - mx);
        p_sm[h * SLEN + s] = e;
        sum += e;
    }
    #pragma unroll
    for (int off = 16; off > 0; off >>= 1)
        sum += __shfl_xor_sync(0xffffffffu, sum, off);
    float inv = 1.f / sum;
    for (int s = lane; s < SLEN; s += 32) p_sm[h * SLEN + s] *= inv;
    __syncthreads();

    {
        int sg  = lane >> 3;
        int c4  = (lane & 7) << 2;
        float4 acc4 = make_float4(0.f, 0.f, 0.f, 0.f);
        const float* ph = p_sm + h * SLEN;
        #pragma unroll 4
        for (int s = sg; s < SLEN; s += 4) {
            float p = ph[s];
            float4 v4 = *reinterpret_cast<const float4*>(vrow + (size_t)s * CH + c4);
            acc4.x = fmaf(p, v4.x, acc4.x);
            acc4.y = fmaf(p, v4.y, acc4.y);
            acc4.z = fmaf(p, v4.z, acc4.z);
            acc4.w = fmaf(p, v4.w, acc4.w);
        }
        #pragma unroll
        for (int off = 8; off <= 16; off <<= 1) {
            acc4.x += __shfl_xor_sync(0xffffffffu, acc4.x, off);
            acc4.y += __shfl_xor_sync(0xffffffffu, acc4.y, off);
            acc4.z += __shfl_xor_sync(0xffffffffu, acc4.z, off);
            acc4.w += __shfl_xor_sync(0xffffffffu, acc4.w, off);
        }
        if (sg == 0)
            *reinterpret_cast<float4*>(g_o_buf + n * HC + h * CH + c4) = acc4;
    }
}

// ---------------------------------------------------------------------------
// Kernel 4: tensor-core out_kernel (bf16x3), BM=64, 256 threads, 2 CTAs/SM,
// cp.async double-buffered weight chunks.
// ---------------------------------------------------------------------------
#define A_STR   264
#define AH_OFF  0                 // 64 x 264 bf16 = 33792 B
#define AL_OFF  33792
#define B0_OFF  67584             // stage s at B0 + s*16896; hi then lo (+8448)
#define BG_OFF  101376
#define OV_OFF  102400
#define BO_OFF  103424
#define SMEM_BYTES 104448

__device__ __forceinline__ void out_prefetch(unsigned sbase, int stage,
        const __nv_bfloat16* __restrict__ WHi,
        const __nv_bfloat16* __restrict__ WLo, int kk, int t) {
    unsigned bh = sbase + B0_OFF + stage * 16896;
    #pragma unroll
    for (int i = 0; i < 2; i++) {
        int f = t + i * 256;
        int row = f >> 5, c8 = (f & 31) << 3;
        unsigned off = (row * A_STR + c8) * 2;
        cp16(bh + off,        WHi + (kk + row) * 256 + c8);
        cp16(bh + 8448 + off, WLo + (kk + row) * 256 + c8);
    }
}

__device__ __forceinline__ void gemm_bf16x3(
    unsigned sbase,
    const __nv_bfloat16* __restrict__ WHi,
    const __nv_bfloat16* __restrict__ WLo,
    float acc[16][4], int t, int lane, int wm, int wn)
{
    out_prefetch(sbase, 0, WHi, WLo, 0, t);
    CP_COMMIT();
    for (int c = 0; c < 16; c++) {
        if (c < 15) { out_prefetch(sbase, (c + 1) & 1, WHi, WLo, (c + 1) * 16, t);
                      CP_COMMIT(); CP_WAIT1(); }
        else        { CP_WAIT0(); }
        __syncthreads();
        int kk = c * 16, s = c & 1;
        unsigned bhb = sbase + B0_OFF + s * 16896;

        unsigned ah[4], al[4];
        unsigned aaddr = sbase + AH_OFF +
            ((wm * 16 + (lane & 15)) * A_STR + kk + ((lane >> 4) << 3)) * 2;
        ldsm4(ah, aaddr);
        ldsm4(al, aaddr + AL_OFF);

        #pragma unroll
        for (int nb = 0; nb < 8; nb++) {
            int n0 = wn * 128 + nb * 16;
            unsigned baddr = bhb +
                ((lane & 15) * A_STR + n0 + ((lane >> 4) << 3)) * 2;
            unsigned bh4[4], bl4[4];
            ldsm4t(bh4, baddr);
            ldsm4t(bl4, baddr + 8448);
            mma_bf16(acc[nb * 2],     ah, bh4[0], bh4[1]);
            mma_bf16(acc[nb * 2],     ah, bl4[0], bl4[1]);
            mma_bf16(acc[nb * 2],     al, bh4[0], bh4[1]);
            mma_bf16(acc[nb * 2 + 1], ah, bh4[2], bh4[3]);
            mma_bf16(acc[nb * 2 + 1], ah, bl4[2], bl4[3]);
            mma_bf16(acc[nb * 2 + 1], al, bh4[2], bh4[3]);
        }
        __syncthreads();
    }
}

__global__ void __launch_bounds__(256, 2)
out_kernel(const float* __restrict__ m,
           const float* __restrict__ bg,
           const float* __restrict__ bo,
           float* __restrict__ out) {
    extern __shared__ char smc[];
    unsigned sbase = (unsigned)__cvta_generic_to_shared(smc);
    float* sBG = reinterpret_cast<float*>(smc + BG_OFF);
    float* sOV = reinterpret_cast<float*>(smc + OV_OFF);
    float* sBO = reinterpret_cast<float*>(smc + BO_OFF);

    int t = threadIdx.x;
    int lane = t & 31, wid = t >> 5;
    int wm = wid >> 1, wn = wid & 1;
    int n = blockIdx.y;
    long tok0 = (long)n * SLEN + (long)blockIdx.x * 64;

    sBG[t] = bg[t];
    sOV[t] = g_o_buf[n * HC + t];
    sBO[t] = bo[t];

    // load m tile [64][256] fp32 once, split into bf16 hi/lo smem
    #pragma unroll
    for (int i = 0; i < 16; i++) {
        int idx = t + i * 256;
        int row = idx >> 6;
        int c4  = (idx & 63) << 2;
        float4 v = *reinterpret_cast<const float4*>(m + (tok0 + row) * CIN + c4);
        split_store(smc + AH_OFF + (row * A_STR + c4) * 2,
                    smc + AL_OFF + (row * A_STR + c4) * 2, v);
    }
    __syncthreads();

    float acc[16][4];
    #pragma unroll
    for (int i = 0; i < 16; i++)
        #pragma unroll
        for (int j = 0; j < 4; j++) acc[i][j] = 0.f;

    // ---- GEMM1: M @ Wg ----
    gemm_bf16x3(sbase, g_WgHi, g_WgLo, acc, t, lane, wm, wn);

    // ---- epilogue 1: G = ov * sigmoid(acc + bg), split back into Ah/Al ----
    #pragma unroll
    for (int nt = 0; nt < 16; nt++) {
        int col0 = wn * 128 + nt * 8 + (lane & 3) * 2;
        int r0   = wm * 16 + (lane >> 2);
        float bg0 = sBG[col0], bg1 = sBG[col0 + 1];
        float ov0 = sOV[col0], ov1 = sOV[col0 + 1];
        float g0 = ov0 / (1.f + __expf(-(acc[nt][0] + bg0)));
        float g1 = ov1 / (1.f + __expf(-(acc[nt][1] + bg1)));
        float g2 = ov0 / (1.f + __expf(-(acc[nt][2] + bg0)));
        float g3 = ov1 / (1.f + __expf(-(acc[nt][3] + bg1)));
        __nv_bfloat162 h01 = __floats2bfloat162_rn(g0, g1);
        __nv_bfloat162 l01 = __floats2bfloat162_rn(g0 - __low2float(h01),
                                                   g1 - __high2float(h01));
        __nv_bfloat162 h23 = __floats2bfloat162_rn(g2, g3);
        __nv_bfloat162 l23 = __floats2bfloat162_rn(g2 - __low2float(h23),
                                                   g3 - __high2float(h23));
        *reinterpret_cast<__nv_bfloat162*>(smc + AH_OFF + (r0 * A_STR + col0) * 2)       = h01;
        *reinterpret_cast<__nv_bfloat162*>(smc + AL_OFF + (r0 * A_STR + col0) * 2)       = l01;
        *reinterpret_cast<__nv_bfloat162*>(smc + AH_OFF + ((r0 + 8) * A_STR + col0) * 2) = h23;
        *reinterpret_cast<__nv_bfloat162*>(smc + AL_OFF + ((r0 + 8) * A_STR + col0) * 2) = l23;
        acc[nt][0] = acc[nt][1] = acc[nt][2] = acc[nt][3] = 0.f;
    }
    __syncthreads();

    // ---- GEMM2: G @ Wo ----
    gemm_bf16x3(sbase, g_WoHi, g_WoLo, acc, t, lane, wm, wn);

    // ---- epilogue 2: + bo, write out ----
    #pragma unroll
    for (int nt = 0; nt < 16; nt++) {
        int col0 = wn * 128 + nt * 8 + (lane & 3) * 2;
        int r0   = wm * 16 + (lane >> 2);
        float2 o0 = make_float2(acc[nt][0] + sBO[col0], acc[nt][1] + sBO[col0 + 1]);
        float2 o1 = make_float2(acc[nt][2] + sBO[col0], acc[nt][3] + sBO[col0 + 1]);
        *reinterpret_cast<float2*>(out + (tok0 + r0) * CIN + col0)     = o0;
        *reinterpret_cast<float2*>(out + (tok0 + r0 + 8) * CIN + col0) = o1;
    }
}

// ---------------------------------------------------------------------------
extern "C" void kernel_launch(void* const* d_in, const int* in_sizes, int n_in,
                              void* d_out, int out_size) {
    const float* m    = (const float*)d_in[0];
    const float* mask = (const float*)d_in[1];
    const float* Wq   = (const float*)d_in[2];
    const float* Wk   = (const float*)d_in[3];
    const float* Wv   = (const float*)d_in[4];
    const float* Wg   = (const float*)d_in[5];
    const float* bg   = (const float*)d_in[6];
    const float* Wo   = (const float*)d_in[7];
    const float* bo   = (const float*)d_in[8];
    float* out = (float*)d_out;

    wconv_kernel<<<64, 256>>>(Wg, Wo, Wk, Wv);

    cudaFuncSetAttribute(kv_kernel,
                         cudaFuncAttributeMaxDynamicSharedMemorySize, KV_SMEM);
    kv_kernel<<<(NROWS * SLEN) / 128, 256, KV_SMEM>>>(m, mask);

    q2_kernel<<<NROWS, 256>>>(Wq);

    attn_kernel<<<NROWS, 256>>>(mask);

    cudaFuncSetAttribute(out_kernel,
                         cudaFuncAttributeMaxDynamicSharedMemorySize, SMEM_BYTES);
    out_kernel<<<dim3(SLEN / 64, NROWS), 256, SMEM_BYTES>>>(m, bg, bo, out);
}